// round 6
// baseline (speedup 1.0000x reference)
#include <cuda_runtime.h>
#include <cuda_bf16.h>

// PairTabAtomicModel: tabulated pair potential atomic energy.
// Shapes (fixed):
//   extended_coord : [8, 16384, 3] f32
//   tab_data       : [4, 4, 2000, 4] f32
//   tab_info       : [4] f32  (rmin, hh, nspline, ntypes)
//   extended_atype : [8, 16384] i32
//   nlist          : [8, 8192, 128] i32
//   out            : [8, 8192, 1] f32
//
// Numerical contract (derived from R2-R5 flip-count algebra, all additive):
// reference (XLA-GPU) computes, bit-exactly:
//   s2 = fma(dz,dz, fma(dx,dx, dy*dy))   // LLVM contracts operand-0 fmul:
//                                        // fadd(dx*dx, dy*dy) -> fma(dx,dx, dy*dy)
//   rr = sqrt.rn.f32(s2)
//   uu = div.full.f32(rr - rmin, hh)     // XLA-GPU f32 divide (not div.rn)

#define NFRAMES 8
#define NLOC    8192
#define NNEI    128
#define NALL    16384
#define RCUT_F  6.0f

__device__ __forceinline__ float div_full(float a, float b) {
    float r;
    asm("div.full.f32 %0, %1, %2;" : "=f"(r) : "f"(a), "f"(b));
    return r;
}

__global__ __launch_bounds__(256)
void pairtab_energy_kernel(const float* __restrict__ coord,
                           const float* __restrict__ tab_data,
                           const float* __restrict__ tab_info,
                           const int*   __restrict__ atype,
                           const int*   __restrict__ nlist,
                           float*       __restrict__ out)
{
    const int gtid    = blockIdx.x * blockDim.x + threadIdx.x;
    const int warp_id = gtid >> 5;            // one warp per (frame, atom) row
    const int lane    = threadIdx.x & 31;
    const int total_rows = NFRAMES * NLOC;
    if (warp_id >= total_rows) return;

    const int f = warp_id / NLOC;
    const int l = warp_id - f * NLOC;

    const float rmin    = tab_info[0];
    const float hh      = tab_info[1];
    const int   nspline = (int)tab_info[2];
    const int   ntypes  = (int)tab_info[3];
    const float rmax    = __fadd_rn(rmin, __fmul_rn((float)nspline, hh));

    const float* __restrict__ cbase = coord + (size_t)f * (size_t)NALL * 3;
    const int*   __restrict__ tbase = atype + (size_t)f * NALL;

    const float xi = cbase[l * 3 + 0];
    const float yi = cbase[l * 3 + 1];
    const float zi = cbase[l * 3 + 2];
    const int   ti = tbase[l];

    const int* __restrict__ nl_row = nlist + (size_t)warp_id * NNEI;

    float sum = 0.0f;

    #pragma unroll
    for (int k = 0; k < NNEI / 32; k++) {
        const int n = lane + k * 32;           // coalesced 128B per step
        const int j = nl_row[n];
        if (j >= 0) {
            // --- bin-determining path (bit-match XLA GPU) ---
            const float dx = __fsub_rn(cbase[j * 3 + 0], xi);
            const float dy = __fsub_rn(cbase[j * 3 + 1], yi);
            const float dz = __fsub_rn(cbase[j * 3 + 2], zi);
            // fma(dz,dz, fma(dx,dx, dy*dy)) : operand-0 contraction order
            const float s2 = __fmaf_rn(dz, dz,
                             __fmaf_rn(dx, dx,
                             __fmul_rn(dy, dy)));
            const float rr = __fsqrt_rn(s2);                      // correctly rounded
            const float uu = div_full(__fsub_rn(rr, rmin), hh);   // XLA-GPU divide

            const int   idx  = (int)uu;                 // trunc, matches astype(int32)
            const float frac = __fsub_rn(uu, (float)idx);
            int clip = idx;
            if (clip < 0) clip = 0;
            if (clip > nspline - 1) clip = nspline - 1;

            const int tj = tbase[j];

            float4 c = make_float4(0.f, 0.f, 0.f, 0.f);
            if (idx <= nspline) {
                const size_t off = ((size_t)(ti * ntypes + tj) * (size_t)nspline + (size_t)clip) * 4;
                c = *reinterpret_cast<const float4*>(tab_data + off);
            }

            // continuous in frac: default codegen fine
            float e = ((c.x * frac + c.y) * frac + c.z) * frac + c.w;
            if (rr >= RCUT_F || rr >= rmax) e = 0.0f;
            sum += e;
        }
    }

    // warp butterfly reduction
    #pragma unroll
    for (int off = 16; off > 0; off >>= 1)
        sum += __shfl_xor_sync(0xffffffffu, sum, off);

    if (lane == 0)
        out[warp_id] = 0.5f * sum;
}

extern "C" void kernel_launch(void* const* d_in, const int* in_sizes, int n_in,
                              void* d_out, int out_size)
{
    const float* coord    = (const float*)d_in[0];
    const float* tab_data = (const float*)d_in[1];
    const float* tab_info = (const float*)d_in[2];
    const int*   atype    = (const int*)d_in[3];
    const int*   nlist    = (const int*)d_in[4];
    float*       out      = (float*)d_out;

    const int total_rows = NFRAMES * NLOC;      // 65536 warps
    const int threads = 256;                    // 8 warps / block
    const int blocks  = (total_rows * 32 + threads - 1) / threads;  // 8192
    pairtab_energy_kernel<<<blocks, threads>>>(coord, tab_data, tab_info,
                                               atype, nlist, out);
}

// round 7
// speedup vs baseline: 1.4475x; 1.4475x over previous
#include <cuda_runtime.h>
#include <cuda_bf16.h>

// PairTabAtomicModel: tabulated pair potential atomic energy.
// Shapes (fixed):
//   extended_coord : [8, 16384, 3] f32
//   tab_data       : [4, 4, 2000, 4] f32
//   tab_info       : [4] f32  (rmin, hh, nspline, ntypes)
//   extended_atype : [8, 16384] i32
//   nlist          : [8, 8192, 128] i32
//   out            : [8, 8192, 1] f32
//
// Numerical contract (locked in R6, bit-matches XLA-GPU):
//   s2 = fma(dz,dz, fma(dx,dx, dy*dy))
//   rr = sqrt.rn.f32(s2)
//   uu = div.full.f32(rr - rmin, hh)
//
// R7 optimization: pack (x,y,z,atype) into one float4 per atom in a prologue
// kernel so the per-neighbor gather is a single aligned LDG.128 instead of
// 3x LDG.32 + 1x LDG.32 (L1tex wavefront-bound at 78.6% in R6). nlist read
// vectorized to int4 per lane for MLP.

#define NFRAMES 8
#define NLOC    8192
#define NNEI    128
#define NALL    16384
#define RCUT_F  6.0f

__device__ float4 g_coord4[NFRAMES * NALL];   // 2 MB scratch (x,y,z,bitcast type)

__device__ __forceinline__ float div_full(float a, float b) {
    float r;
    asm("div.full.f32 %0, %1, %2;" : "=f"(r) : "f"(a), "f"(b));
    return r;
}

__global__ __launch_bounds__(256)
void pack_coord4_kernel(const float* __restrict__ coord,
                        const int*   __restrict__ atype)
{
    const int i = blockIdx.x * blockDim.x + threadIdx.x;
    if (i < NFRAMES * NALL) {
        float4 v;
        v.x = coord[i * 3 + 0];
        v.y = coord[i * 3 + 1];
        v.z = coord[i * 3 + 2];
        v.w = __int_as_float(atype[i]);
        g_coord4[i] = v;
    }
}

__global__ __launch_bounds__(256)
void pairtab_energy_kernel(const float* __restrict__ tab_data,
                           const float* __restrict__ tab_info,
                           const int*   __restrict__ nlist,
                           float*       __restrict__ out)
{
    const int gtid    = blockIdx.x * blockDim.x + threadIdx.x;
    const int warp_id = gtid >> 5;            // one warp per (frame, atom) row
    const int lane    = threadIdx.x & 31;
    const int total_rows = NFRAMES * NLOC;
    if (warp_id >= total_rows) return;

    const int f = warp_id / NLOC;
    const int l = warp_id - f * NLOC;

    const float rmin    = tab_info[0];
    const float hh      = tab_info[1];
    const int   nspline = (int)tab_info[2];
    const int   ntypes  = (int)tab_info[3];
    const float rmax    = __fadd_rn(rmin, __fmul_rn((float)nspline, hh));

    const float4* __restrict__ cb4 = g_coord4 + (size_t)f * NALL;

    const float4 ci = cb4[l];
    const float xi = ci.x, yi = ci.y, zi = ci.z;
    const int   ti = __float_as_int(ci.w);
    const float* __restrict__ tab_i = tab_data + (size_t)ti * ntypes * nspline * 4;

    const int* __restrict__ nl_row = nlist + (size_t)warp_id * NNEI;

    float sum = 0.0f;

    // each lane owns 4 consecutive neighbors via one int4 load (coalesced 512B/warp)
    const int4 jj = *reinterpret_cast<const int4*>(nl_row + lane * 4);
    const int js[4] = { jj.x, jj.y, jj.z, jj.w };

    #pragma unroll
    for (int k = 0; k < 4; k++) {
        const int j = js[k];
        if (j >= 0) {
            const float4 cj = cb4[j];                 // single LDG.128 gather
            // --- bin-determining path (bit-match XLA GPU, locked) ---
            const float dx = __fsub_rn(cj.x, xi);
            const float dy = __fsub_rn(cj.y, yi);
            const float dz = __fsub_rn(cj.z, zi);
            const float s2 = __fmaf_rn(dz, dz,
                             __fmaf_rn(dx, dx,
                             __fmul_rn(dy, dy)));
            const float rr = __fsqrt_rn(s2);
            const float uu = div_full(__fsub_rn(rr, rmin), hh);

            const int   idx  = (int)uu;               // trunc, matches astype(int32)
            const float frac = __fsub_rn(uu, (float)idx);
            int clip = idx;
            if (clip < 0) clip = 0;
            if (clip > nspline - 1) clip = nspline - 1;

            const int tj = __float_as_int(cj.w);

            float4 c = make_float4(0.f, 0.f, 0.f, 0.f);
            if (idx <= nspline) {
                const size_t off = ((size_t)tj * (size_t)nspline + (size_t)clip) * 4;
                c = *reinterpret_cast<const float4*>(tab_i + off);
            }

            float e = ((c.x * frac + c.y) * frac + c.z) * frac + c.w;
            if (rr >= RCUT_F || rr >= rmax) e = 0.0f;
            sum += e;
        }
    }

    // warp butterfly reduction
    #pragma unroll
    for (int off = 16; off > 0; off >>= 1)
        sum += __shfl_xor_sync(0xffffffffu, sum, off);

    if (lane == 0)
        out[warp_id] = 0.5f * sum;
}

extern "C" void kernel_launch(void* const* d_in, const int* in_sizes, int n_in,
                              void* d_out, int out_size)
{
    const float* coord    = (const float*)d_in[0];
    const float* tab_data = (const float*)d_in[1];
    const float* tab_info = (const float*)d_in[2];
    const int*   atype    = (const int*)d_in[3];
    const int*   nlist    = (const int*)d_in[4];
    float*       out      = (float*)d_out;

    // prologue: pack coords + types into float4 scratch
    {
        const int n = NFRAMES * NALL;                 // 131072
        pack_coord4_kernel<<<(n + 255) / 256, 256>>>(coord, atype);
    }

    const int total_rows = NFRAMES * NLOC;            // 65536 warps
    const int threads = 256;                          // 8 warps / block
    const int blocks  = (total_rows * 32 + threads - 1) / threads;  // 8192
    pairtab_energy_kernel<<<blocks, threads>>>(tab_data, tab_info, nlist, out);
}

// round 8
// speedup vs baseline: 1.7323x; 1.1968x over previous
#include <cuda_runtime.h>
#include <cuda_bf16.h>

// PairTabAtomicModel: tabulated pair potential atomic energy.
// Shapes (fixed):
//   extended_coord : [8, 16384, 3] f32
//   tab_data       : [4, 4, 2000, 4] f32
//   tab_info       : [4] f32  (rmin, hh, nspline, ntypes)
//   extended_atype : [8, 16384] i32
//   nlist          : [8, 8192, 128] i32
//   out            : [8, 8192, 1] f32
//
// Numerical contract (locked in R6, bit-matches XLA-GPU):
//   s2 = fma(dz,dz, fma(dx,dx, dy*dy))
//   rr = sqrt.rn.f32(s2)
//   uu = div.full.f32(rr - rmin, hh)
//
// R7: packed (x,y,z,atype) float4 scratch -> 1 gather LDG.128 per neighbor.
// R8: skip the 16B tab_data gather whenever the energy is zeroed anyway
//     (rr >= RCUT or rr >= rmax): ~40% of pairs, pure L1tex wavefront waste.

#define NFRAMES 8
#define NLOC    8192
#define NNEI    128
#define NALL    16384
#define RCUT_F  6.0f

__device__ float4 g_coord4[NFRAMES * NALL];   // 2 MB scratch (x,y,z,bitcast type)

__device__ __forceinline__ float div_full(float a, float b) {
    float r;
    asm("div.full.f32 %0, %1, %2;" : "=f"(r) : "f"(a), "f"(b));
    return r;
}

__global__ __launch_bounds__(256)
void pack_coord4_kernel(const float* __restrict__ coord,
                        const int*   __restrict__ atype)
{
    const int i = blockIdx.x * blockDim.x + threadIdx.x;
    if (i < NFRAMES * NALL) {
        float4 v;
        v.x = coord[i * 3 + 0];
        v.y = coord[i * 3 + 1];
        v.z = coord[i * 3 + 2];
        v.w = __int_as_float(atype[i]);
        g_coord4[i] = v;
    }
}

__global__ __launch_bounds__(256)
void pairtab_energy_kernel(const float* __restrict__ tab_data,
                           const float* __restrict__ tab_info,
                           const int*   __restrict__ nlist,
                           float*       __restrict__ out)
{
    const int gtid    = blockIdx.x * blockDim.x + threadIdx.x;
    const int warp_id = gtid >> 5;            // one warp per (frame, atom) row
    const int lane    = threadIdx.x & 31;
    const int total_rows = NFRAMES * NLOC;
    if (warp_id >= total_rows) return;

    const int f = warp_id / NLOC;
    const int l = warp_id - f * NLOC;

    const float rmin    = tab_info[0];
    const float hh      = tab_info[1];
    const int   nspline = (int)tab_info[2];
    const int   ntypes  = (int)tab_info[3];
    const float rmax    = __fadd_rn(rmin, __fmul_rn((float)nspline, hh));

    const float4* __restrict__ cb4 = g_coord4 + (size_t)f * NALL;

    const float4 ci = cb4[l];
    const float xi = ci.x, yi = ci.y, zi = ci.z;
    const int   ti = __float_as_int(ci.w);
    const float* __restrict__ tab_i = tab_data + (size_t)ti * ntypes * nspline * 4;

    const int* __restrict__ nl_row = nlist + (size_t)warp_id * NNEI;

    float sum = 0.0f;

    // each lane owns 4 consecutive neighbors via one int4 load (coalesced 512B/warp)
    const int4 jj = *reinterpret_cast<const int4*>(nl_row + lane * 4);
    const int js[4] = { jj.x, jj.y, jj.z, jj.w };

    #pragma unroll
    for (int k = 0; k < 4; k++) {
        const int j = js[k];
        if (j >= 0) {
            const float4 cj = cb4[j];                 // single LDG.128 gather
            // --- bin-determining path (bit-match XLA GPU, locked) ---
            const float dx = __fsub_rn(cj.x, xi);
            const float dy = __fsub_rn(cj.y, yi);
            const float dz = __fsub_rn(cj.z, zi);
            const float s2 = __fmaf_rn(dz, dz,
                             __fmaf_rn(dx, dx,
                             __fmul_rn(dy, dy)));
            const float rr = __fsqrt_rn(s2);

            // contribution predicate: reference zeroes e when rr >= RCUT or
            // rr >= rmax (and idx>nspline is implied by rr>=rmax). Skip the
            // tab gather entirely for those (~40% of unmasked pairs).
            if (rr < RCUT_F && rr < rmax) {
                const float uu = div_full(__fsub_rn(rr, rmin), hh);

                const int   idx  = (int)uu;           // trunc, matches astype(int32)
                const float frac = __fsub_rn(uu, (float)idx);
                int clip = idx;
                if (clip < 0) clip = 0;
                if (clip > nspline - 1) clip = nspline - 1;

                const int tj = __float_as_int(cj.w);
                const size_t off = ((size_t)tj * (size_t)nspline + (size_t)clip) * 4;
                const float4 c = *reinterpret_cast<const float4*>(tab_i + off);

                sum += ((c.x * frac + c.y) * frac + c.z) * frac + c.w;
            }
        }
    }

    // warp butterfly reduction
    #pragma unroll
    for (int off = 16; off > 0; off >>= 1)
        sum += __shfl_xor_sync(0xffffffffu, sum, off);

    if (lane == 0)
        out[warp_id] = 0.5f * sum;
}

extern "C" void kernel_launch(void* const* d_in, const int* in_sizes, int n_in,
                              void* d_out, int out_size)
{
    const float* coord    = (const float*)d_in[0];
    const float* tab_data = (const float*)d_in[1];
    const float* tab_info = (const float*)d_in[2];
    const int*   atype    = (const int*)d_in[3];
    const int*   nlist    = (const int*)d_in[4];
    float*       out      = (float*)d_out;

    // prologue: pack coords + types into float4 scratch
    {
        const int n = NFRAMES * NALL;                 // 131072
        pack_coord4_kernel<<<(n + 255) / 256, 256>>>(coord, atype);
    }

    const int total_rows = NFRAMES * NLOC;            // 65536 warps
    const int threads = 256;                          // 8 warps / block
    const int blocks  = (total_rows * 32 + threads - 1) / threads;  // 8192
    pairtab_energy_kernel<<<blocks, threads>>>(tab_data, tab_info, nlist, out);
}